// round 3
// baseline (speedup 1.0000x reference)
#include <cuda_runtime.h>

// MaskedCommonWeightSimpleLinearGNN, algebraically refactored:
//   w = LW * A  (binary mask, ~1% dense, 8192x8192), same w all 3 layers.
//   out = (w^3 x) M + (w^2 1) c0^T + (w 1) c1^T + 1 b2^T
//     M  = W0^T W1^T W2^T,  c0 = W2 W1 b0,  c1 = W2 b1
// Pipeline: build ELL (+row sums s1) -> tiny dense preps -> s2 = w s1 ->
//           spmm(x), spmm, spmm_final (M + rank-1 epilogue fused).

#define NN   8192
#define DD   64
#define CAP  192      // Binomial(8192,0.01): mean 82, sigma 9 -> enormous margin
#define RPB  16       // rows per block in SpMM

// ---- allocation-free scratch ----
__device__ int   g_cnt[NN];
__device__ int   g_cols[(size_t)NN * CAP];
__device__ float g_vals[(size_t)NN * CAP];
__device__ float g_s1[NN];
__device__ float g_s2[NN];
__device__ float g_P[DD * DD];
__device__ float g_M[DD * DD];
__device__ float g_q[DD];
__device__ float g_c0[DD];
__device__ float g_c1[DD];
__device__ float g_buf0[(size_t)NN * DD];
__device__ float g_buf1[(size_t)NN * DD];

// ============================================================================
// 1) Build ELL: one warp per row, depth-2 prefetched A scan (MLP=2 per warp),
//    ballot compaction, sparse gather of LW, row-sum s1 on the fly.
// ============================================================================
__global__ void build_ell_kernel(const float* __restrict__ A,
                                 const float* __restrict__ LW) {
    int row  = blockIdx.x * (blockDim.x >> 5) + (threadIdx.x >> 5);
    int lane = threadIdx.x & 31;
    if (row >= NN) return;

    const float4* a4 = reinterpret_cast<const float4*>(A + (size_t)row * NN);
    const float*  lw = LW + (size_t)row * NN;
    int*   cols = g_cols + (size_t)row * CAP;
    float* vals = g_vals + (size_t)row * CAP;

    int   cnt  = 0;
    float ssum = 0.0f;

    float4 p0 = a4[lane];             // chunk 0
    float4 p1 = a4[32 + lane];        // chunk 1
    for (int c = 0; c < NN / 128; ++c) {
        float4 nx;
        if (c + 2 < NN / 128) nx = a4[(c + 2) * 32 + lane];  // keep 2 in flight
        float a[4] = {p0.x, p0.y, p0.z, p0.w};
        #pragma unroll
        for (int r = 0; r < 4; ++r) {
            bool nz = (a[r] != 0.0f);
            unsigned m = __ballot_sync(0xffffffffu, nz);
            if (nz) {
                int pos = cnt + __popc(m & ((1u << lane) - 1u));
                if (pos < CAP) {
                    int col = c * 128 + lane * 4 + r;
                    float v = lw[col];
                    cols[pos] = col;
                    vals[pos] = v;
                    ssum += v;
                }
            }
            cnt += __popc(m);
        }
        p0 = p1;
        p1 = nx;
    }
    #pragma unroll
    for (int o = 16; o; o >>= 1) ssum += __shfl_xor_sync(0xffffffffu, ssum, o);
    if (lane == 0) {
        g_cnt[row] = (cnt < CAP) ? cnt : CAP;
        g_s1[row]  = ssum;
    }
}

// ============================================================================
// 2) prep1: P = W0^T W1^T; block 0 also q = W1 b0 and c1 = W2 b1.
// ============================================================================
__global__ void prep1_kernel(const float* __restrict__ W0,
                             const float* __restrict__ W1,
                             const float* __restrict__ b0,
                             const float* __restrict__ W2,
                             const float* __restrict__ b1) {
    __shared__ float sW0[DD * DD];
    __shared__ float sW1[DD * DD];
    int tid = threadIdx.x;
    for (int i = tid; i < DD * DD; i += 256) { sW0[i] = W0[i]; sW1[i] = W1[i]; }
    __syncthreads();

    int base = blockIdx.x * 1024;
    for (int j = 0; j < 4; ++j) {
        int idx = base + j * 256 + tid;
        int d = idx >> 6, e = idx & 63;
        float s = 0.0f;
        #pragma unroll
        for (int f = 0; f < DD; ++f) s += sW0[f * DD + d] * sW1[e * DD + f];
        g_P[idx] = s;
    }
    if (blockIdx.x == 0 && tid < DD) {
        float s = 0.0f;
        #pragma unroll
        for (int d = 0; d < DD; ++d) s += sW1[tid * DD + d] * b0[d];
        g_q[tid] = s;
        float s2 = 0.0f;
        #pragma unroll
        for (int d = 0; d < DD; ++d) s2 += W2[tid * DD + d] * b1[d];
        g_c1[tid] = s2;
    }
}

// ============================================================================
// 3) prep2: M[d,t] = sum_e P[d,e] W2[t,e];  block 0: c0 = W2 q.
// ============================================================================
__global__ void prep2_kernel(const float* __restrict__ W2) {
    __shared__ float sP[DD * DD];
    __shared__ float sW2[DD * DD];
    int tid = threadIdx.x;
    for (int i = tid; i < DD * DD; i += 256) { sP[i] = g_P[i]; sW2[i] = W2[i]; }
    __syncthreads();

    int base = blockIdx.x * 1024;
    for (int j = 0; j < 4; ++j) {
        int idx = base + j * 256 + tid;
        int d = idx >> 6, t = idx & 63;
        float s = 0.0f;
        #pragma unroll
        for (int e = 0; e < DD; ++e) s += sP[d * DD + e] * sW2[t * DD + e];
        g_M[idx] = s;
    }
    if (blockIdx.x == 0 && tid < DD) {
        float s = 0.0f;
        #pragma unroll
        for (int e = 0; e < DD; ++e) s += sW2[tid * DD + e] * g_q[e];
        g_c0[tid] = s;
    }
}

// ============================================================================
// 4) s2 = w s1   (warp per row)
// ============================================================================
__global__ void s2_kernel() {
    int row  = blockIdx.x * 4 + (threadIdx.x >> 5);
    int lane = threadIdx.x & 31;
    const int*   cr = g_cols + (size_t)row * CAP;
    const float* vr = g_vals + (size_t)row * CAP;
    int cnt = g_cnt[row];
    float s = 0.0f;
    for (int k = lane; k < cnt; k += 32) s += vr[k] * g_s1[cr[k]];
    #pragma unroll
    for (int o = 16; o; o >>= 1) s += __shfl_xor_sync(0xffffffffu, s, o);
    if (lane == 0) g_s2[row] = s;
}

// ============================================================================
// 5) SpMM: xout = w @ xin. 16 rows/block, 256 threads (16 lanes per row),
//    cols/vals staged in shared, 4-way unrolled float4 gathers (MLP=4).
// ============================================================================
__global__ void __launch_bounds__(256)
spmm_kernel(const float* __restrict__ xin, float* __restrict__ xout) {
    __shared__ int   sC[RPB * CAP];
    __shared__ float sV[RPB * CAP];
    __shared__ int   sCnt[RPB];

    int tid  = threadIdx.x;
    int row0 = blockIdx.x * RPB;

    if (tid < RPB) sCnt[tid] = g_cnt[row0 + tid];
    const int*   gc = g_cols + (size_t)row0 * CAP;
    const float* gv = g_vals + (size_t)row0 * CAP;
    #pragma unroll
    for (int j = 0; j < (RPB * CAP) / 256; ++j) {
        int i = j * 256 + tid;
        sC[i] = gc[i];
        sV[i] = gv[i];
    }
    __syncthreads();

    int r = tid >> 4, l = tid & 15;
    int cnt = sCnt[r];
    const int*   cr = sC + r * CAP;
    const float* vr = sV + r * CAP;
    const float4* x4 = reinterpret_cast<const float4*>(xin);

    float4 a0 = make_float4(0.f,0.f,0.f,0.f), a1 = a0, a2 = a0, a3 = a0;
    int k = 0;
    for (; k + 4 <= cnt; k += 4) {
        int   c0 = cr[k],  c1 = cr[k+1], c2 = cr[k+2], c3 = cr[k+3];
        float v0 = vr[k],  v1 = vr[k+1], v2 = vr[k+2], v3 = vr[k+3];
        float4 g0 = __ldg(&x4[c0 * 16 + l]);
        float4 g1 = __ldg(&x4[c1 * 16 + l]);
        float4 g2 = __ldg(&x4[c2 * 16 + l]);
        float4 g3 = __ldg(&x4[c3 * 16 + l]);
        a0.x += v0*g0.x; a0.y += v0*g0.y; a0.z += v0*g0.z; a0.w += v0*g0.w;
        a1.x += v1*g1.x; a1.y += v1*g1.y; a1.z += v1*g1.z; a1.w += v1*g1.w;
        a2.x += v2*g2.x; a2.y += v2*g2.y; a2.z += v2*g2.z; a2.w += v2*g2.w;
        a3.x += v3*g3.x; a3.y += v3*g3.y; a3.z += v3*g3.z; a3.w += v3*g3.w;
    }
    for (; k < cnt; ++k) {
        int c = cr[k]; float v = vr[k];
        float4 g = __ldg(&x4[c * 16 + l]);
        a0.x += v*g.x; a0.y += v*g.y; a0.z += v*g.z; a0.w += v*g.w;
    }
    float4 acc;
    acc.x = (a0.x + a1.x) + (a2.x + a3.x);
    acc.y = (a0.y + a1.y) + (a2.y + a3.y);
    acc.z = (a0.z + a1.z) + (a2.z + a3.z);
    acc.w = (a0.w + a1.w) + (a2.w + a3.w);

    reinterpret_cast<float4*>(xout)[(size_t)(row0 + r) * 16 + l] = acc;
}

// ============================================================================
// 6) Final SpMM with fused epilogue: out = (w y) M + s2 c0^T + s1 c1^T + b2
// ============================================================================
__global__ void __launch_bounds__(256)
spmm_final_kernel(const float* __restrict__ xin, float* __restrict__ xout,
                  const float* __restrict__ b2) {
    __shared__ int   sC[RPB * CAP];
    __shared__ float sV[RPB * CAP];
    __shared__ int   sCnt[RPB];
    __shared__ float sM[DD * DD];       // 16 KB
    __shared__ float shY[RPB][DD];      // 4 KB

    int tid  = threadIdx.x;
    int row0 = blockIdx.x * RPB;

    if (tid < RPB) sCnt[tid] = g_cnt[row0 + tid];
    // stage M (overlaps with cols/vals staging in the LSU queue)
    #pragma unroll
    for (int j = 0; j < (DD * DD) / 256; ++j) sM[j * 256 + tid] = g_M[j * 256 + tid];

    const int*   gc = g_cols + (size_t)row0 * CAP;
    const float* gv = g_vals + (size_t)row0 * CAP;
    #pragma unroll
    for (int j = 0; j < (RPB * CAP) / 256; ++j) {
        int i = j * 256 + tid;
        sC[i] = gc[i];
        sV[i] = gv[i];
    }
    __syncthreads();

    int r = tid >> 4, l = tid & 15;
    int cnt = sCnt[r];
    const int*   cr = sC + r * CAP;
    const float* vr = sV + r * CAP;
    const float4* x4 = reinterpret_cast<const float4*>(xin);

    float4 a0 = make_float4(0.f,0.f,0.f,0.f), a1 = a0, a2 = a0, a3 = a0;
    int k = 0;
    for (; k + 4 <= cnt; k += 4) {
        int   c0 = cr[k],  c1 = cr[k+1], c2 = cr[k+2], c3 = cr[k+3];
        float v0 = vr[k],  v1 = vr[k+1], v2 = vr[k+2], v3 = vr[k+3];
        float4 g0 = __ldg(&x4[c0 * 16 + l]);
        float4 g1 = __ldg(&x4[c1 * 16 + l]);
        float4 g2 = __ldg(&x4[c2 * 16 + l]);
        float4 g3 = __ldg(&x4[c3 * 16 + l]);
        a0.x += v0*g0.x; a0.y += v0*g0.y; a0.z += v0*g0.z; a0.w += v0*g0.w;
        a1.x += v1*g1.x; a1.y += v1*g1.y; a1.z += v1*g1.z; a1.w += v1*g1.w;
        a2.x += v2*g2.x; a2.y += v2*g2.y; a2.z += v2*g2.z; a2.w += v2*g2.w;
        a3.x += v3*g3.x; a3.y += v3*g3.y; a3.z += v3*g3.z; a3.w += v3*g3.w;
    }
    for (; k < cnt; ++k) {
        int c = cr[k]; float v = vr[k];
        float4 g = __ldg(&x4[c * 16 + l]);
        a0.x += v*g.x; a0.y += v*g.y; a0.z += v*g.z; a0.w += v*g.w;
    }
    float4 y;
    y.x = (a0.x + a1.x) + (a2.x + a3.x);
    y.y = (a0.y + a1.y) + (a2.y + a3.y);
    y.z = (a0.z + a1.z) + (a2.z + a3.z);
    y.w = (a0.w + a1.w) + (a2.w + a3.w);

    // stash y row tile, then apply M
    reinterpret_cast<float4*>(&shY[r][0])[l] = y;
    __syncthreads();

    int row = row0 + r;
    float s1v = g_s1[row], s2v = g_s2[row];
    float4 c0v = reinterpret_cast<const float4*>(g_c0)[l];
    float4 c1v = reinterpret_cast<const float4*>(g_c1)[l];
    float4 bv  = __ldg(&reinterpret_cast<const float4*>(b2)[l]);

    float4 acc;
    acc.x = s2v * c0v.x + s1v * c1v.x + bv.x;
    acc.y = s2v * c0v.y + s1v * c1v.y + bv.y;
    acc.z = s2v * c0v.z + s1v * c1v.z + bv.z;
    acc.w = s2v * c0v.w + s1v * c1v.w + bv.w;

    #pragma unroll 8
    for (int d = 0; d < DD; ++d) {
        float yd  = shY[r][d];
        float4 m4 = reinterpret_cast<const float4*>(sM + d * DD)[l];
        acc.x += yd * m4.x; acc.y += yd * m4.y;
        acc.z += yd * m4.z; acc.w += yd * m4.w;
    }

    reinterpret_cast<float4*>(xout)[(size_t)row * 16 + l] = acc;
}

// ============================================================================
// Launch
// ============================================================================
extern "C" void kernel_launch(void* const* d_in, const int* in_sizes, int n_in,
                              void* d_out, int out_size) {
    const float* x  = (const float*)d_in[0];
    const float* A  = (const float*)d_in[1];
    const float* LW = (const float*)d_in[2];
    const float* W0 = (const float*)d_in[3];
    const float* b0 = (const float*)d_in[4];
    const float* W1 = (const float*)d_in[5];
    const float* b1 = (const float*)d_in[6];
    const float* W2 = (const float*)d_in[7];
    const float* b2 = (const float*)d_in[8];
    float* out = (float*)d_out;

    float* buf0; cudaGetSymbolAddress((void**)&buf0, g_buf0);
    float* buf1; cudaGetSymbolAddress((void**)&buf1, g_buf1);

    build_ell_kernel<<<NN / 8, 256>>>(A, LW);        // ELL + s1
    prep1_kernel<<<4, 256>>>(W0, W1, b0, W2, b1);    // P, q, c1
    prep2_kernel<<<4, 256>>>(W2);                    // M, c0
    s2_kernel<<<NN / 4, 128>>>();                    // s2 = w s1

    spmm_kernel<<<NN / RPB, 256>>>(x,    buf0);      // y1 = w x
    spmm_kernel<<<NN / RPB, 256>>>(buf0, buf1);      // y2 = w y1
    spmm_final_kernel<<<NN / RPB, 256>>>(buf1, out, b2);  // out = (w y2)M + rank-1
}

// round 4
// speedup vs baseline: 1.2205x; 1.2205x over previous
#include <cuda_runtime.h>

// MaskedCommonWeightSimpleLinearGNN, refactored:
//   w = LW * A (binary mask ~1%, 8192x8192), same w all 3 layers.
//   out = (w^3 x) M + (w^2 1) c0^T + (w 1) c1^T + 1 b2^T
//     M = W0^T W1^T W2^T, c0 = W2 W1 b0, c1 = W2 b1
// Pipeline:
//   scan   : A -> compacted cols (ushort) + cnt        (pure streaming)
//   gather : vals[k] = LW[row][cols[k]], s1 = row sums (pure gather)
//   prep1/2: M, c0, c1 (tiny dense)
//   spmm x3: y = w y; layer2 also computes s2 = w s1; layer3 fuses
//            M + rank-1 epilogue.

#define NN   8192
#define DD   64
#define CAP  192      // Binomial(8192,0.01): mean 82, sigma 9
#define RPB  16

// ---- allocation-free scratch ----
__device__ unsigned short g_cols[(size_t)NN * CAP];   // 3 MB
__device__ float          g_vals[(size_t)NN * CAP];   // 6 MB
__device__ int            g_cnt[NN];
__device__ float          g_s1[NN];
__device__ float          g_s2[NN];
__device__ float          g_P[DD * DD];
__device__ float          g_M[DD * DD];
__device__ float          g_q[DD];
__device__ float          g_c0[DD];
__device__ float          g_c1[DD];
__device__ float          g_buf0[(size_t)NN * DD];
__device__ float          g_buf1[(size_t)NN * DD];

// ============================================================================
// 1a) scan: one warp per row. Streaming float4 scan of A, one warp
//     shuffle-scan per 128-col chunk, compacted ushort column writes.
//     NO LW access -> no dependent gathers in the streaming loop.
// ============================================================================
__global__ void scan_kernel(const float* __restrict__ A) {
    int row  = blockIdx.x * 8 + (threadIdx.x >> 5);
    int lane = threadIdx.x & 31;

    const float4* a4 = reinterpret_cast<const float4*>(A + (size_t)row * NN);
    unsigned short* cols = g_cols + (size_t)row * CAP;

    int cnt = 0;
    float4 cur = a4[lane];                          // prefetch chunk 0
    for (int c = 0; c < NN / 128; ++c) {
        float4 nxt;
        if (c + 1 < NN / 128) nxt = a4[(c + 1) * 32 + lane];

        unsigned m = 0;
        if (cur.x != 0.0f) m |= 1u;
        if (cur.y != 0.0f) m |= 2u;
        if (cur.z != 0.0f) m |= 4u;
        if (cur.w != 0.0f) m |= 8u;
        int nl  = __popc(m);

        // inclusive warp scan of nl
        int inc = nl;
        #pragma unroll
        for (int o = 1; o < 32; o <<= 1) {
            int t = __shfl_up_sync(0xffffffffu, inc, o);
            if (lane >= o) inc += t;
        }
        int pos = cnt + inc - nl;                   // exclusive prefix
        int cb  = c * 128 + lane * 4;
        if (m & 1u) { if (pos < CAP) cols[pos] = (unsigned short)(cb    ); ++pos; }
        if (m & 2u) { if (pos < CAP) cols[pos] = (unsigned short)(cb + 1); ++pos; }
        if (m & 4u) { if (pos < CAP) cols[pos] = (unsigned short)(cb + 2); ++pos; }
        if (m & 8u) { if (pos < CAP) cols[pos] = (unsigned short)(cb + 3); ++pos; }

        cnt += __shfl_sync(0xffffffffu, inc, 31);   // warp total
        cur = nxt;
    }
    if (lane == 0) g_cnt[row] = (cnt < CAP) ? cnt : CAP;
}

// ============================================================================
// 1b) gather: vals[k] = LW[row][cols[k]]; s1[row] = sum vals. One warp/row,
//     fully unrolled predicated loop -> 6 independent gathers in flight/lane.
// ============================================================================
__global__ void gather_kernel(const float* __restrict__ LW) {
    int row  = blockIdx.x * 8 + (threadIdx.x >> 5);
    int lane = threadIdx.x & 31;

    const float* lw = LW + (size_t)row * NN;
    const unsigned short* cols = g_cols + (size_t)row * CAP;
    float* vals = g_vals + (size_t)row * CAP;
    int cnt = g_cnt[row];

    float s = 0.0f;
    #pragma unroll
    for (int j = 0; j < CAP / 32; ++j) {
        int k = j * 32 + lane;
        if (k < cnt) {
            float v = __ldg(&lw[cols[k]]);
            vals[k] = v;
            s += v;
        }
    }
    #pragma unroll
    for (int o = 16; o; o >>= 1) s += __shfl_xor_sync(0xffffffffu, s, o);
    if (lane == 0) g_s1[row] = s;
}

// ============================================================================
// 2) prep1: P = W0^T W1^T; block 0 also q = W1 b0, c1 = W2 b1.
// ============================================================================
__global__ void prep1_kernel(const float* __restrict__ W0,
                             const float* __restrict__ W1,
                             const float* __restrict__ b0,
                             const float* __restrict__ W2,
                             const float* __restrict__ b1) {
    __shared__ float sW0[DD * DD];
    __shared__ float sW1[DD * DD];
    int tid = threadIdx.x;
    for (int i = tid; i < DD * DD; i += 256) { sW0[i] = W0[i]; sW1[i] = W1[i]; }
    __syncthreads();

    int base = blockIdx.x * 1024;
    for (int j = 0; j < 4; ++j) {
        int idx = base + j * 256 + tid;
        int d = idx >> 6, e = idx & 63;
        float s = 0.0f;
        #pragma unroll
        for (int f = 0; f < DD; ++f) s += sW0[f * DD + d] * sW1[e * DD + f];
        g_P[idx] = s;
    }
    if (blockIdx.x == 0 && tid < DD) {
        float s = 0.0f;
        #pragma unroll
        for (int d = 0; d < DD; ++d) s += sW1[tid * DD + d] * b0[d];
        g_q[tid] = s;
        float s2 = 0.0f;
        #pragma unroll
        for (int d = 0; d < DD; ++d) s2 += W2[tid * DD + d] * b1[d];
        g_c1[tid] = s2;
    }
}

// ============================================================================
// 3) prep2: M[d,t] = sum_e P[d,e] W2[t,e]; block 0: c0 = W2 q.
// ============================================================================
__global__ void prep2_kernel(const float* __restrict__ W2) {
    __shared__ float sP[DD * DD];
    __shared__ float sW2[DD * DD];
    int tid = threadIdx.x;
    for (int i = tid; i < DD * DD; i += 256) { sP[i] = g_P[i]; sW2[i] = W2[i]; }
    __syncthreads();

    int base = blockIdx.x * 1024;
    for (int j = 0; j < 4; ++j) {
        int idx = base + j * 256 + tid;
        int d = idx >> 6, t = idx & 63;
        float s = 0.0f;
        #pragma unroll
        for (int e = 0; e < DD; ++e) s += sP[d * DD + e] * sW2[t * DD + e];
        g_M[idx] = s;
    }
    if (blockIdx.x == 0 && tid < DD) {
        float s = 0.0f;
        #pragma unroll
        for (int e = 0; e < DD; ++e) s += sW2[tid * DD + e] * g_q[e];
        g_c0[tid] = s;
    }
}

// ============================================================================
// 4) SpMM template. 16 rows/block, 256 threads (16 lanes/row).
//    cols (ushort) + vals staged in shared; 4-way unrolled float4 gathers.
//    S2: lanes 0-3 also accumulate s2 = sum v * s1[col].
//    FINAL: fused epilogue out = y M + s2 c0^T + s1 c1^T + b2.
// ============================================================================
template <bool S2, bool FINAL>
__global__ void __launch_bounds__(256)
spmm_kernel(const float* __restrict__ xin, float* __restrict__ xout,
            const float* __restrict__ b2) {
    __shared__ unsigned short sC[RPB * CAP];     // 6 KB
    __shared__ float          sV[RPB * CAP];     // 12 KB
    __shared__ int            sCnt[RPB];
    __shared__ float          sM[FINAL ? DD * DD : 1];
    __shared__ float          shY[FINAL ? RPB : 1][DD];

    int tid  = threadIdx.x;
    int row0 = blockIdx.x * RPB;

    if (tid < RPB) sCnt[tid] = g_cnt[row0 + tid];

    // stage cols as uint2 (4 ushorts), vals as float4
    {
        const uint2* gc2 = reinterpret_cast<const uint2*>(g_cols + (size_t)row0 * CAP);
        uint2* sC2 = reinterpret_cast<uint2*>(sC);
        #pragma unroll
        for (int j = 0; j < (RPB * CAP / 4) / 256; ++j)
            sC2[j * 256 + tid] = gc2[j * 256 + tid];
        const float4* gv4 = reinterpret_cast<const float4*>(g_vals + (size_t)row0 * CAP);
        float4* sV4 = reinterpret_cast<float4*>(sV);
        #pragma unroll
        for (int j = 0; j < (RPB * CAP / 4) / 256; ++j)
            sV4[j * 256 + tid] = gv4[j * 256 + tid];
        if (FINAL) {
            const float4* gm4 = reinterpret_cast<const float4*>(g_M);
            float4* sM4 = reinterpret_cast<float4*>(sM);
            #pragma unroll
            for (int j = 0; j < (DD * DD / 4) / 256; ++j)
                sM4[j * 256 + tid] = gm4[j * 256 + tid];
        }
    }
    __syncthreads();

    int r = tid >> 4, l = tid & 15;
    int cnt = sCnt[r];
    const unsigned short* cr = sC + r * CAP;
    const float*          vr = sV + r * CAP;
    const float4* x4 = reinterpret_cast<const float4*>(xin);

    float4 a0 = make_float4(0.f,0.f,0.f,0.f), a1 = a0, a2 = a0, a3 = a0;
    float s2a = 0.0f;
    int k = 0;
    for (; k + 4 <= cnt; k += 4) {
        int   c0 = cr[k],  c1 = cr[k+1], c2 = cr[k+2], c3 = cr[k+3];
        float v0 = vr[k],  v1 = vr[k+1], v2 = vr[k+2], v3 = vr[k+3];
        float4 g0 = __ldg(&x4[c0 * 16 + l]);
        float4 g1 = __ldg(&x4[c1 * 16 + l]);
        float4 g2 = __ldg(&x4[c2 * 16 + l]);
        float4 g3 = __ldg(&x4[c3 * 16 + l]);
        if (S2) {
            if      (l == 0) s2a += v0 * __ldg(&g_s1[c0]);
            else if (l == 1) s2a += v1 * __ldg(&g_s1[c1]);
            else if (l == 2) s2a += v2 * __ldg(&g_s1[c2]);
            else if (l == 3) s2a += v3 * __ldg(&g_s1[c3]);
        }
        a0.x += v0*g0.x; a0.y += v0*g0.y; a0.z += v0*g0.z; a0.w += v0*g0.w;
        a1.x += v1*g1.x; a1.y += v1*g1.y; a1.z += v1*g1.z; a1.w += v1*g1.w;
        a2.x += v2*g2.x; a2.y += v2*g2.y; a2.z += v2*g2.z; a2.w += v2*g2.w;
        a3.x += v3*g3.x; a3.y += v3*g3.y; a3.z += v3*g3.z; a3.w += v3*g3.w;
    }
    for (; k < cnt; ++k) {
        int c = cr[k]; float v = vr[k];
        float4 g = __ldg(&x4[c * 16 + l]);
        if (S2 && l == 0) s2a += v * __ldg(&g_s1[c]);
        a0.x += v*g.x; a0.y += v*g.y; a0.z += v*g.z; a0.w += v*g.w;
    }
    float4 y;
    y.x = (a0.x + a1.x) + (a2.x + a3.x);
    y.y = (a0.y + a1.y) + (a2.y + a3.y);
    y.z = (a0.z + a1.z) + (a2.z + a3.z);
    y.w = (a0.w + a1.w) + (a2.w + a3.w);

    int row = row0 + r;

    if (S2) {
        s2a += __shfl_xor_sync(0xffffffffu, s2a, 1);
        s2a += __shfl_xor_sync(0xffffffffu, s2a, 2);
        if (l == 0) g_s2[row] = s2a;
    }

    if (!FINAL) {
        reinterpret_cast<float4*>(xout)[(size_t)row * 16 + l] = y;
    } else {
        reinterpret_cast<float4*>(&shY[r][0])[l] = y;
        __syncthreads();

        float s1v = g_s1[row], s2v = g_s2[row];
        float4 c0v = reinterpret_cast<const float4*>(g_c0)[l];
        float4 c1v = reinterpret_cast<const float4*>(g_c1)[l];
        float4 bv  = __ldg(&reinterpret_cast<const float4*>(b2)[l]);

        float4 acc;
        acc.x = s2v * c0v.x + s1v * c1v.x + bv.x;
        acc.y = s2v * c0v.y + s1v * c1v.y + bv.y;
        acc.z = s2v * c0v.z + s1v * c1v.z + bv.z;
        acc.w = s2v * c0v.w + s1v * c1v.w + bv.w;

        #pragma unroll 8
        for (int d = 0; d < DD; ++d) {
            float yd  = shY[r][d];
            float4 m4 = reinterpret_cast<const float4*>(sM + d * DD)[l];
            acc.x += yd * m4.x; acc.y += yd * m4.y;
            acc.z += yd * m4.z; acc.w += yd * m4.w;
        }
        reinterpret_cast<float4*>(xout)[(size_t)row * 16 + l] = acc;
    }
}

// ============================================================================
// Launch
// ============================================================================
extern "C" void kernel_launch(void* const* d_in, const int* in_sizes, int n_in,
                              void* d_out, int out_size) {
    const float* x  = (const float*)d_in[0];
    const float* A  = (const float*)d_in[1];
    const float* LW = (const float*)d_in[2];
    const float* W0 = (const float*)d_in[3];
    const float* b0 = (const float*)d_in[4];
    const float* W1 = (const float*)d_in[5];
    const float* b1 = (const float*)d_in[6];
    const float* W2 = (const float*)d_in[7];
    const float* b2 = (const float*)d_in[8];
    float* out = (float*)d_out;

    float* buf0; cudaGetSymbolAddress((void**)&buf0, g_buf0);
    float* buf1; cudaGetSymbolAddress((void**)&buf1, g_buf1);

    scan_kernel  <<<NN / 8, 256>>>(A);              // cols + cnt
    gather_kernel<<<NN / 8, 256>>>(LW);             // vals + s1
    prep1_kernel <<<4, 256>>>(W0, W1, b0, W2, b1);  // P, q, c1
    prep2_kernel <<<4, 256>>>(W2);                  // M, c0

    spmm_kernel<false, false><<<NN / RPB, 256>>>(x,    buf0, nullptr);  // y1
    spmm_kernel<true,  false><<<NN / RPB, 256>>>(buf0, buf1, nullptr);  // y2 + s2
    spmm_kernel<false, true ><<<NN / RPB, 256>>>(buf1, out,  b2);       // out
}

// round 5
// speedup vs baseline: 1.3871x; 1.1365x over previous
#include <cuda_runtime.h>

// MaskedCommonWeightSimpleLinearGNN:
//   w = LW * A (binary mask ~1%, 8192x8192), same w for all 3 layers.
//   out = (w^3 x) M + (w^2 1) c0^T + (w 1) c1^T + 1 b2^T
//     M = W0^T W1^T W2^T, c0 = W2 W1 b0, c1 = W2 b1
// Pipeline (5 launches):
//   build  : scan A (streaming) -> cols in SMEM -> gather LW -> cols/vals/s1
//   prep   : M, c0, c1 (one kernel, 16 blocks, conflict-free)
//   spmm x3: y = w y; layer2 also s2 = w s1; layer3 fuses M + rank-1 epilogue.

#define NN   8192
#define DD   64
#define CAP  192      // Binomial(8192,0.01): mean 82, sigma 9
#define RPB  16

// ---- allocation-free scratch ----
__device__ unsigned short g_cols[(size_t)NN * CAP];   // 3 MB
__device__ float          g_vals[(size_t)NN * CAP];   // 6 MB
__device__ int            g_cnt[NN];
__device__ float          g_s1[NN];
__device__ float          g_s2[NN];
__device__ float          g_M[DD * DD];
__device__ float          g_c0[DD];
__device__ float          g_c1[DD];
__device__ float          g_buf0[(size_t)NN * DD];
__device__ float          g_buf1[(size_t)NN * DD];

// ============================================================================
// 1) build: one warp per row. Streaming float4 scan of A with warp
//    shuffle-scan compaction into a per-warp SMEM cols buffer; then a
//    predicated unrolled LW gather (MLP=6/lane) + cols/vals/s1 writeout.
// ============================================================================
__global__ void __launch_bounds__(256)
build_kernel(const float* __restrict__ A, const float* __restrict__ LW) {
    __shared__ unsigned short sCols[8][CAP];

    int wid  = threadIdx.x >> 5;
    int lane = threadIdx.x & 31;
    int row  = blockIdx.x * 8 + wid;

    const float4* a4 = reinterpret_cast<const float4*>(A + (size_t)row * NN);
    unsigned short* wc = sCols[wid];

    int cnt = 0;
    float4 cur = a4[lane];                          // prefetch chunk 0
    for (int c = 0; c < NN / 128; ++c) {
        float4 nxt;
        if (c + 1 < NN / 128) nxt = a4[(c + 1) * 32 + lane];

        unsigned m = 0;
        if (cur.x != 0.0f) m |= 1u;
        if (cur.y != 0.0f) m |= 2u;
        if (cur.z != 0.0f) m |= 4u;
        if (cur.w != 0.0f) m |= 8u;
        int nl = __popc(m);

        // inclusive warp scan of nl
        int inc = nl;
        #pragma unroll
        for (int o = 1; o < 32; o <<= 1) {
            int t = __shfl_up_sync(0xffffffffu, inc, o);
            if (lane >= o) inc += t;
        }
        int pos = cnt + inc - nl;                   // exclusive prefix
        int cb  = c * 128 + lane * 4;
        if (m & 1u) { if (pos < CAP) wc[pos] = (unsigned short)(cb    ); ++pos; }
        if (m & 2u) { if (pos < CAP) wc[pos] = (unsigned short)(cb + 1); ++pos; }
        if (m & 4u) { if (pos < CAP) wc[pos] = (unsigned short)(cb + 2); ++pos; }
        if (m & 8u) { if (pos < CAP) wc[pos] = (unsigned short)(cb + 3); ++pos; }

        cnt += __shfl_sync(0xffffffffu, inc, 31);
        cur = nxt;
    }
    if (cnt > CAP) cnt = CAP;
    __syncwarp();

    // gather phase: vals[k] = LW[row][cols[k]], coalesced writeout, row sum
    const float* lw = LW + (size_t)row * NN;
    unsigned short* gcols = g_cols + (size_t)row * CAP;
    float*          gvals = g_vals + (size_t)row * CAP;

    float s = 0.0f;
    #pragma unroll
    for (int j = 0; j < CAP / 32; ++j) {
        int k = j * 32 + lane;
        if (k < cnt) {
            unsigned short c = wc[k];
            float v = __ldg(&lw[c]);
            gvals[k] = v;
            gcols[k] = c;
            s += v;
        }
    }
    #pragma unroll
    for (int o = 16; o; o >>= 1) s += __shfl_xor_sync(0xffffffffu, s, o);
    if (lane == 0) {
        g_cnt[row] = cnt;
        g_s1[row]  = s;
    }
}

// ============================================================================
// 2) prep: M = W0^T W1^T W2^T, c0 = W2 W1 b0, c1 = W2 b1.
//    16 blocks x 256 threads; block b owns M rows [4b, 4b+4).
//    All shared arrays padded (stride 65) -> conflict-free.
// ============================================================================
__global__ void __launch_bounds__(256)
prep_kernel(const float* __restrict__ W0, const float* __restrict__ W1,
            const float* __restrict__ b0, const float* __restrict__ W2,
            const float* __restrict__ b1) {
    __shared__ float sW0[DD * DD];        // accessed [f*64+d], d const/warp -> bcast
    __shared__ float sW1[DD * 65];        // [e][f] padded
    __shared__ float sW2[DD * 65];        // [t][e] padded
    __shared__ float sP[4 * 65];          // P rows for this block
    __shared__ float sQ[DD];

    int tid = threadIdx.x;
    for (int i = tid; i < DD * DD; i += 256) {
        sW0[i] = W0[i];
        sW1[(i >> 6) * 65 + (i & 63)] = W1[i];
        sW2[(i >> 6) * 65 + (i & 63)] = W2[i];
    }
    __syncthreads();

    int dl = tid >> 6;                    // 0..3 local row
    int e  = tid & 63;
    int d  = blockIdx.x * 4 + dl;

    // P[d,e] = sum_f W0[f,d] * W1[e,f]
    float p = 0.0f;
    #pragma unroll
    for (int f = 0; f < DD; ++f) p += sW0[f * DD + d] * sW1[e * 65 + f];
    sP[dl * 65 + e] = p;

    // block 0: q = W1 b0
    if (blockIdx.x == 0 && tid < DD) {
        float s = 0.0f;
        #pragma unroll
        for (int f = 0; f < DD; ++f) s += sW1[tid * 65 + f] * __ldg(&b0[f]);
        sQ[tid] = s;
    }
    __syncthreads();

    // M[d,t] = sum_e P[d,e] * W2[t,e]
    int t = e;
    float msum = 0.0f;
    #pragma unroll
    for (int ee = 0; ee < DD; ++ee) msum += sP[dl * 65 + ee] * sW2[t * 65 + ee];
    g_M[d * DD + t] = msum;

    // block 0: c0 = W2 q, c1 = W2 b1
    if (blockIdx.x == 0 && tid < DD) {
        float s0 = 0.0f, s1v = 0.0f;
        #pragma unroll
        for (int ee = 0; ee < DD; ++ee) {
            float w2 = sW2[tid * 65 + ee];
            s0  += w2 * sQ[ee];
            s1v += w2 * __ldg(&b1[ee]);
        }
        g_c0[tid] = s0;
        g_c1[tid] = s1v;
    }
}

// ============================================================================
// 3) SpMM template. 16 rows/block, 256 threads (16 lanes/row).
//    cols (ushort) + vals staged in shared; 4-way unrolled float4 gathers.
//    S2: lanes 0-3 also accumulate s2 = sum v * s1[col].
//    FINAL: fused epilogue out = y M + s2 c0^T + s1 c1^T + b2.
// ============================================================================
template <bool S2, bool FINAL>
__global__ void __launch_bounds__(256)
spmm_kernel(const float* __restrict__ xin, float* __restrict__ xout,
            const float* __restrict__ b2) {
    __shared__ unsigned short sC[RPB * CAP];     // 6 KB
    __shared__ float          sV[RPB * CAP];     // 12 KB
    __shared__ int            sCnt[RPB];
    __shared__ float          sM[FINAL ? DD * DD : 1];
    __shared__ float          shY[FINAL ? RPB : 1][DD];

    int tid  = threadIdx.x;
    int row0 = blockIdx.x * RPB;

    if (tid < RPB) sCnt[tid] = g_cnt[row0 + tid];

    {
        const uint2* gc2 = reinterpret_cast<const uint2*>(g_cols + (size_t)row0 * CAP);
        uint2* sC2 = reinterpret_cast<uint2*>(sC);
        #pragma unroll
        for (int j = 0; j < (RPB * CAP / 4) / 256; ++j)
            sC2[j * 256 + tid] = gc2[j * 256 + tid];
        const float4* gv4 = reinterpret_cast<const float4*>(g_vals + (size_t)row0 * CAP);
        float4* sV4 = reinterpret_cast<float4*>(sV);
        #pragma unroll
        for (int j = 0; j < (RPB * CAP / 4) / 256; ++j)
            sV4[j * 256 + tid] = gv4[j * 256 + tid];
        if (FINAL) {
            const float4* gm4 = reinterpret_cast<const float4*>(g_M);
            float4* sM4 = reinterpret_cast<float4*>(sM);
            #pragma unroll
            for (int j = 0; j < (DD * DD / 4) / 256; ++j)
                sM4[j * 256 + tid] = gm4[j * 256 + tid];
        }
    }
    __syncthreads();

    int r = tid >> 4, l = tid & 15;
    int cnt = sCnt[r];
    const unsigned short* cr = sC + r * CAP;
    const float*          vr = sV + r * CAP;
    const float4* x4 = reinterpret_cast<const float4*>(xin);

    float4 a0 = make_float4(0.f,0.f,0.f,0.f), a1 = a0, a2 = a0, a3 = a0;
    float s2a = 0.0f;
    int k = 0;
    for (; k + 4 <= cnt; k += 4) {
        int   c0 = cr[k],  c1 = cr[k+1], c2 = cr[k+2], c3 = cr[k+3];
        float v0 = vr[k],  v1 = vr[k+1], v2 = vr[k+2], v3 = vr[k+3];
        float4 g0 = __ldg(&x4[c0 * 16 + l]);
        float4 g1 = __ldg(&x4[c1 * 16 + l]);
        float4 g2 = __ldg(&x4[c2 * 16 + l]);
        float4 g3 = __ldg(&x4[c3 * 16 + l]);
        if (S2) {
            if      (l == 0) s2a += v0 * __ldg(&g_s1[c0]);
            else if (l == 1) s2a += v1 * __ldg(&g_s1[c1]);
            else if (l == 2) s2a += v2 * __ldg(&g_s1[c2]);
            else if (l == 3) s2a += v3 * __ldg(&g_s1[c3]);
        }
        a0.x += v0*g0.x; a0.y += v0*g0.y; a0.z += v0*g0.z; a0.w += v0*g0.w;
        a1.x += v1*g1.x; a1.y += v1*g1.y; a1.z += v1*g1.z; a1.w += v1*g1.w;
        a2.x += v2*g2.x; a2.y += v2*g2.y; a2.z += v2*g2.z; a2.w += v2*g2.w;
        a3.x += v3*g3.x; a3.y += v3*g3.y; a3.z += v3*g3.z; a3.w += v3*g3.w;
    }
    for (; k < cnt; ++k) {
        int c = cr[k]; float v = vr[k];
        float4 g = __ldg(&x4[c * 16 + l]);
        if (S2 && l == 0) s2a += v * __ldg(&g_s1[c]);
        a0.x += v*g.x; a0.y += v*g.y; a0.z += v*g.z; a0.w += v*g.w;
    }
    float4 y;
    y.x = (a0.x + a1.x) + (a2.x + a3.x);
    y.y = (a0.y + a1.y) + (a2.y + a3.y);
    y.z = (a0.z + a1.z) + (a2.z + a3.z);
    y.w = (a0.w + a1.w) + (a2.w + a3.w);

    int row = row0 + r;

    if (S2) {
        s2a += __shfl_xor_sync(0xffffffffu, s2a, 1);
        s2a += __shfl_xor_sync(0xffffffffu, s2a, 2);
        if (l == 0) g_s2[row] = s2a;
    }

    if (!FINAL) {
        reinterpret_cast<float4*>(xout)[(size_t)row * 16 + l] = y;
    } else {
        reinterpret_cast<float4*>(&shY[r][0])[l] = y;
        __syncthreads();

        float s1v = g_s1[row], s2v = g_s2[row];
        float4 c0v = reinterpret_cast<const float4*>(g_c0)[l];
        float4 c1v = reinterpret_cast<const float4*>(g_c1)[l];
        float4 bv  = __ldg(&reinterpret_cast<const float4*>(b2)[l]);

        float4 acc;
        acc.x = s2v * c0v.x + s1v * c1v.x + bv.x;
        acc.y = s2v * c0v.y + s1v * c1v.y + bv.y;
        acc.z = s2v * c0v.z + s1v * c1v.z + bv.z;
        acc.w = s2v * c0v.w + s1v * c1v.w + bv.w;

        #pragma unroll 8
        for (int d = 0; d < DD; ++d) {
            float yd  = shY[r][d];
            float4 m4 = reinterpret_cast<const float4*>(sM + d * DD)[l];
            acc.x += yd * m4.x; acc.y += yd * m4.y;
            acc.z += yd * m4.z; acc.w += yd * m4.w;
        }
        reinterpret_cast<float4*>(xout)[(size_t)row * 16 + l] = acc;
    }
}

// ============================================================================
// Launch (5 kernels)
// ============================================================================
extern "C" void kernel_launch(void* const* d_in, const int* in_sizes, int n_in,
                              void* d_out, int out_size) {
    const float* x  = (const float*)d_in[0];
    const float* A  = (const float*)d_in[1];
    const float* LW = (const float*)d_in[2];
    const float* W0 = (const float*)d_in[3];
    const float* b0 = (const float*)d_in[4];
    const float* W1 = (const float*)d_in[5];
    const float* b1 = (const float*)d_in[6];
    const float* W2 = (const float*)d_in[7];
    const float* b2 = (const float*)d_in[8];
    float* out = (float*)d_out;

    float* buf0; cudaGetSymbolAddress((void**)&buf0, g_buf0);
    float* buf1; cudaGetSymbolAddress((void**)&buf1, g_buf1);

    build_kernel<<<NN / 8, 256>>>(A, LW);           // cols/vals/cnt/s1
    prep_kernel <<<16, 256>>>(W0, W1, b0, W2, b1);  // M, c0, c1

    spmm_kernel<false, false><<<NN / RPB, 256>>>(x,    buf0, nullptr);  // y1
    spmm_kernel<true,  false><<<NN / RPB, 256>>>(buf0, buf1, nullptr);  // y2 + s2
    spmm_kernel<false, true ><<<NN / RPB, 256>>>(buf1, out,  b2);       // out
}

// round 6
// speedup vs baseline: 1.5242x; 1.0988x over previous
#include <cuda_runtime.h>

// MaskedCommonWeightSimpleLinearGNN:
//   w = LW * A (binary mask ~1%, 8192x8192), same w for all 3 layers.
//   out = (w^3 x) M + (w^2 1) c0^T + (w 1) c1^T + 1 b2^T
//     M = W0^T W1^T W2^T, c0 = W2 W1 b0, c1 = W2 b1
// Pipeline (5 launches):
//   build  : scan A (ballot compaction -> SMEM cols) -> gather LW -> cols/vals/s1
//   prep   : M, c0, c1 (one kernel, conflict-free)
//   spmm x3: y = w y (unroll-8 gathers); layer2 strided-s2; layer3 fused epilogue.

#define NN   8192
#define DD   64
#define CAP  192      // Binomial(8192,0.01): mean 82, sigma 9
#define RPB  16

// ---- allocation-free scratch ----
__device__ unsigned short g_cols[(size_t)NN * CAP];   // 3 MB
__device__ float          g_vals[(size_t)NN * CAP];   // 6 MB
__device__ int            g_cnt[NN];
__device__ float          g_s1[NN];
__device__ float          g_s2[NN];
__device__ float          g_M[DD * DD];
__device__ float          g_c0[DD];
__device__ float          g_c1[DD];
__device__ float          g_buf0[(size_t)NN * DD];
__device__ float          g_buf1[(size_t)NN * DD];

// ============================================================================
// 1) build: one warp per row. Streaming float4 scan of A, ballot compaction
//    (4 independent ballots/chunk, short dep chain) into per-warp SMEM cols;
//    then predicated unrolled LW gather (MLP=6/lane) + cols/vals/s1 writeout.
// ============================================================================
__global__ void __launch_bounds__(256)
build_kernel(const float* __restrict__ A, const float* __restrict__ LW) {
    __shared__ unsigned short sCols[8][CAP];

    int wid  = threadIdx.x >> 5;
    int lane = threadIdx.x & 31;
    int row  = blockIdx.x * 8 + wid;

    const float4* a4 = reinterpret_cast<const float4*>(A + (size_t)row * NN);
    unsigned short* wc = sCols[wid];
    unsigned lt = (1u << lane) - 1u;

    int cnt = 0;
    float4 cur = a4[lane];                          // prefetch chunk 0
    for (int c = 0; c < NN / 128; ++c) {
        float4 nxt;
        if (c + 1 < NN / 128) nxt = a4[(c + 1) * 32 + lane];

        float a[4] = {cur.x, cur.y, cur.z, cur.w};
        int cb = c * 128 + lane * 4;
        #pragma unroll
        for (int r = 0; r < 4; ++r) {
            bool nz = (a[r] != 0.0f);
            unsigned m = __ballot_sync(0xffffffffu, nz);
            if (nz) {
                int pos = cnt + __popc(m & lt);
                if (pos < CAP) wc[pos] = (unsigned short)(cb + r);
            }
            cnt += __popc(m);
        }
        cur = nxt;
    }
    if (cnt > CAP) cnt = CAP;
    __syncwarp();

    // gather phase: vals[k] = LW[row][cols[k]], coalesced writeout, row sum
    const float* lw = LW + (size_t)row * NN;
    unsigned short* gcols = g_cols + (size_t)row * CAP;
    float*          gvals = g_vals + (size_t)row * CAP;

    float s = 0.0f;
    #pragma unroll
    for (int j = 0; j < CAP / 32; ++j) {
        int k = j * 32 + lane;
        if (k < cnt) {
            unsigned short c = wc[k];
            float v = __ldg(&lw[c]);
            gvals[k] = v;
            gcols[k] = c;
            s += v;
        }
    }
    #pragma unroll
    for (int o = 16; o; o >>= 1) s += __shfl_xor_sync(0xffffffffu, s, o);
    if (lane == 0) {
        g_cnt[row] = cnt;
        g_s1[row]  = s;
    }
}

// ============================================================================
// 2) prep: M = W0^T W1^T W2^T, c0 = W2 W1 b0, c1 = W2 b1.
//    16 blocks x 256 threads; padded shared (stride 65) -> conflict-free.
// ============================================================================
__global__ void __launch_bounds__(256)
prep_kernel(const float* __restrict__ W0, const float* __restrict__ W1,
            const float* __restrict__ b0, const float* __restrict__ W2,
            const float* __restrict__ b1) {
    __shared__ float sW0[DD * DD];        // [f*64+d], d const per warp -> broadcast
    __shared__ float sW1[DD * 65];        // [e][f] padded
    __shared__ float sW2[DD * 65];        // [t][e] padded
    __shared__ float sP[4 * 65];
    __shared__ float sQ[DD];

    int tid = threadIdx.x;
    for (int i = tid; i < DD * DD; i += 256) {
        sW0[i] = W0[i];
        sW1[(i >> 6) * 65 + (i & 63)] = W1[i];
        sW2[(i >> 6) * 65 + (i & 63)] = W2[i];
    }
    __syncthreads();

    int dl = tid >> 6;
    int e  = tid & 63;
    int d  = blockIdx.x * 4 + dl;

    float p = 0.0f;
    #pragma unroll
    for (int f = 0; f < DD; ++f) p += sW0[f * DD + d] * sW1[e * 65 + f];
    sP[dl * 65 + e] = p;

    if (blockIdx.x == 0 && tid < DD) {
        float s = 0.0f;
        #pragma unroll
        for (int f = 0; f < DD; ++f) s += sW1[tid * 65 + f] * __ldg(&b0[f]);
        sQ[tid] = s;
    }
    __syncthreads();

    int t = e;
    float msum = 0.0f;
    #pragma unroll
    for (int ee = 0; ee < DD; ++ee) msum += sP[dl * 65 + ee] * sW2[t * 65 + ee];
    g_M[d * DD + t] = msum;

    if (blockIdx.x == 0 && tid < DD) {
        float s0 = 0.0f, s1v = 0.0f;
        #pragma unroll
        for (int ee = 0; ee < DD; ++ee) {
            float w2 = sW2[tid * 65 + ee];
            s0  += w2 * sQ[ee];
            s1v += w2 * __ldg(&b1[ee]);
        }
        g_c0[tid] = s0;
        g_c1[tid] = s1v;
    }
}

// ============================================================================
// 3) SpMM template. 16 rows/block, 256 threads (16 lanes/row).
//    cols (ushort) + vals staged in shared; 8-way unrolled float4 gathers.
//    S2: strided post-loop (lane k-stride 16) computing s2 = w s1.
//    FINAL: fused epilogue out = y M + s2 c0^T + s1 c1^T + b2.
// ============================================================================
template <bool S2, bool FINAL>
__global__ void __launch_bounds__(256)
spmm_kernel(const float* __restrict__ xin, float* __restrict__ xout,
            const float* __restrict__ b2) {
    __shared__ unsigned short sC[RPB * CAP];     // 6 KB
    __shared__ float          sV[RPB * CAP];     // 12 KB
    __shared__ int            sCnt[RPB];
    __shared__ float          sM[FINAL ? DD * DD : 1];
    __shared__ float          shY[FINAL ? RPB : 1][DD];

    int tid  = threadIdx.x;
    int row0 = blockIdx.x * RPB;

    if (tid < RPB) sCnt[tid] = g_cnt[row0 + tid];

    {
        const uint2* gc2 = reinterpret_cast<const uint2*>(g_cols + (size_t)row0 * CAP);
        uint2* sC2 = reinterpret_cast<uint2*>(sC);
        #pragma unroll
        for (int j = 0; j < (RPB * CAP / 4) / 256; ++j)
            sC2[j * 256 + tid] = gc2[j * 256 + tid];
        const float4* gv4 = reinterpret_cast<const float4*>(g_vals + (size_t)row0 * CAP);
        float4* sV4 = reinterpret_cast<float4*>(sV);
        #pragma unroll
        for (int j = 0; j < (RPB * CAP / 4) / 256; ++j)
            sV4[j * 256 + tid] = gv4[j * 256 + tid];
        if (FINAL) {
            const float4* gm4 = reinterpret_cast<const float4*>(g_M);
            float4* sM4 = reinterpret_cast<float4*>(sM);
            #pragma unroll
            for (int j = 0; j < (DD * DD / 4) / 256; ++j)
                sM4[j * 256 + tid] = gm4[j * 256 + tid];
        }
    }
    __syncthreads();

    int r = tid >> 4, l = tid & 15;
    int cnt = sCnt[r];
    const unsigned short* cr = sC + r * CAP;
    const float*          vr = sV + r * CAP;
    const float4* x4 = reinterpret_cast<const float4*>(xin);

    float4 a0 = make_float4(0.f,0.f,0.f,0.f), a1 = a0, a2 = a0, a3 = a0;
    int k = 0;
    // 8-way unrolled: 8 independent gathers in flight per lane
    for (; k + 8 <= cnt; k += 8) {
        int   c0 = cr[k],   c1 = cr[k+1], c2 = cr[k+2], c3 = cr[k+3];
        int   c4 = cr[k+4], c5 = cr[k+5], c6 = cr[k+6], c7 = cr[k+7];
        float v0 = vr[k],   v1 = vr[k+1], v2 = vr[k+2], v3 = vr[k+3];
        float v4 = vr[k+4], v5 = vr[k+5], v6 = vr[k+6], v7 = vr[k+7];
        float4 g0 = __ldg(&x4[c0 * 16 + l]);
        float4 g1 = __ldg(&x4[c1 * 16 + l]);
        float4 g2 = __ldg(&x4[c2 * 16 + l]);
        float4 g3 = __ldg(&x4[c3 * 16 + l]);
        float4 g4 = __ldg(&x4[c4 * 16 + l]);
        float4 g5 = __ldg(&x4[c5 * 16 + l]);
        float4 g6 = __ldg(&x4[c6 * 16 + l]);
        float4 g7 = __ldg(&x4[c7 * 16 + l]);
        a0.x += v0*g0.x; a0.y += v0*g0.y; a0.z += v0*g0.z; a0.w += v0*g0.w;
        a1.x += v1*g1.x; a1.y += v1*g1.y; a1.z += v1*g1.z; a1.w += v1*g1.w;
        a2.x += v2*g2.x; a2.y += v2*g2.y; a2.z += v2*g2.z; a2.w += v2*g2.w;
        a3.x += v3*g3.x; a3.y += v3*g3.y; a3.z += v3*g3.z; a3.w += v3*g3.w;
        a0.x += v4*g4.x; a0.y += v4*g4.y; a0.z += v4*g4.z; a0.w += v4*g4.w;
        a1.x += v5*g5.x; a1.y += v5*g5.y; a1.z += v5*g5.z; a1.w += v5*g5.w;
        a2.x += v6*g6.x; a2.y += v6*g6.y; a2.z += v6*g6.z; a2.w += v6*g6.w;
        a3.x += v7*g7.x; a3.y += v7*g7.y; a3.z += v7*g7.z; a3.w += v7*g7.w;
    }
    for (; k + 4 <= cnt; k += 4) {
        int   c0 = cr[k],  c1 = cr[k+1], c2 = cr[k+2], c3 = cr[k+3];
        float v0 = vr[k],  v1 = vr[k+1], v2 = vr[k+2], v3 = vr[k+3];
        float4 g0 = __ldg(&x4[c0 * 16 + l]);
        float4 g1 = __ldg(&x4[c1 * 16 + l]);
        float4 g2 = __ldg(&x4[c2 * 16 + l]);
        float4 g3 = __ldg(&x4[c3 * 16 + l]);
        a0.x += v0*g0.x; a0.y += v0*g0.y; a0.z += v0*g0.z; a0.w += v0*g0.w;
        a1.x += v1*g1.x; a1.y += v1*g1.y; a1.z += v1*g1.z; a1.w += v1*g1.w;
        a2.x += v2*g2.x; a2.y += v2*g2.y; a2.z += v2*g2.z; a2.w += v2*g2.w;
        a3.x += v3*g3.x; a3.y += v3*g3.y; a3.z += v3*g3.z; a3.w += v3*g3.w;
    }
    for (; k < cnt; ++k) {
        int c = cr[k]; float v = vr[k];
        float4 g = __ldg(&x4[c * 16 + l]);
        a0.x += v*g.x; a0.y += v*g.y; a0.z += v*g.z; a0.w += v*g.w;
    }
    float4 y;
    y.x = (a0.x + a1.x) + (a2.x + a3.x);
    y.y = (a0.y + a1.y) + (a2.y + a3.y);
    y.z = (a0.z + a1.z) + (a2.z + a3.z);
    y.w = (a0.w + a1.w) + (a2.w + a3.w);

    int row = row0 + r;

    if (S2) {
        // strided s2 = sum_k v_k * s1[col_k]; s1 is 32KB -> L2-resident
        float s2a = 0.0f;
        for (int kk = l; kk < cnt; kk += 16)
            s2a += vr[kk] * __ldg(&g_s1[cr[kk]]);
        #pragma unroll
        for (int o = 8; o; o >>= 1) s2a += __shfl_xor_sync(0xffffffffu, s2a, o);
        if (l == 0) g_s2[row] = s2a;
    }

    if (!FINAL) {
        reinterpret_cast<float4*>(xout)[(size_t)row * 16 + l] = y;
    } else {
        reinterpret_cast<float4*>(&shY[r][0])[l] = y;
        __syncthreads();

        float s1v = g_s1[row], s2v = g_s2[row];
        float4 c0v = reinterpret_cast<const float4*>(g_c0)[l];
        float4 c1v = reinterpret_cast<const float4*>(g_c1)[l];
        float4 bv  = __ldg(&reinterpret_cast<const float4*>(b2)[l]);

        float4 acc;
        acc.x = s2v * c0v.x + s1v * c1v.x + bv.x;
        acc.y = s2v * c0v.y + s1v * c1v.y + bv.y;
        acc.z = s2v * c0v.z + s1v * c1v.z + bv.z;
        acc.w = s2v * c0v.w + s1v * c1v.w + bv.w;

        #pragma unroll 8
        for (int d = 0; d < DD; ++d) {
            float yd  = shY[r][d];
            float4 m4 = reinterpret_cast<const float4*>(sM + d * DD)[l];
            acc.x += yd * m4.x; acc.y += yd * m4.y;
            acc.z += yd * m4.z; acc.w += yd * m4.w;
        }
        reinterpret_cast<float4*>(xout)[(size_t)row * 16 + l] = acc;
    }
}

// ============================================================================
// Launch (5 kernels)
// ============================================================================
extern "C" void kernel_launch(void* const* d_in, const int* in_sizes, int n_in,
                              void* d_out, int out_size) {
    const float* x  = (const float*)d_in[0];
    const float* A  = (const float*)d_in[1];
    const float* LW = (const float*)d_in[2];
    const float* W0 = (const float*)d_in[3];
    const float* b0 = (const float*)d_in[4];
    const float* W1 = (const float*)d_in[5];
    const float* b1 = (const float*)d_in[6];
    const float* W2 = (const float*)d_in[7];
    const float* b2 = (const float*)d_in[8];
    float* out = (float*)d_out;

    float* buf0; cudaGetSymbolAddress((void**)&buf0, g_buf0);
    float* buf1; cudaGetSymbolAddress((void**)&buf1, g_buf1);

    build_kernel<<<NN / 8, 256>>>(A, LW);           // cols/vals/cnt/s1
    prep_kernel <<<16, 256>>>(W0, W1, b0, W2, b1);  // M, c0, c1

    spmm_kernel<false, false><<<NN / RPB, 256>>>(x,    buf0, nullptr);  // y1
    spmm_kernel<true,  false><<<NN / RPB, 256>>>(buf0, buf1, nullptr);  // y2 + s2
    spmm_kernel<false, true ><<<NN / RPB, 256>>>(buf1, out,  b2);       // out
}